// round 16
// baseline (speedup 1.0000x reference)
#include <cuda_runtime.h>
#include <cuda_bf16.h>
#include <cstdint>
#include <cstddef>

#define SQ 2048
#define HIDN 2048
#define NHEAD 16
#define NKVH 4
#define HDIM 128
#define QKV_N 3072
#define RECENT_W 204
#define HEAVY_K 204

typedef __nv_bfloat16 bf;
typedef unsigned int u32;

// ---------------- device globals (no allocations allowed) -------------------
__device__ __align__(16) float g_qkv[SQ * QKV_N];
__device__ __align__(16) bf g_hid_h[SQ * HIDN];
__device__ __align__(16) bf g_hid_l[SQ * HIDN];
__device__ __align__(16) bf g_wT_h[(size_t)QKV_N * HIDN];
__device__ __align__(16) bf g_wT_l[(size_t)QKV_N * HIDN];
__device__ __align__(16) bf g_woT_h[(size_t)HIDN * HIDN];
__device__ __align__(16) bf g_woT_l[(size_t)HIDN * HIDN];
__device__ __align__(16) bf g_q_h[NHEAD * SQ * HDIM];
__device__ __align__(16) bf g_q_l[NHEAD * SQ * HDIM];
__device__ __align__(16) bf g_k_h[NKVH * SQ * HDIM];
__device__ __align__(16) bf g_k_l[NKVH * SQ * HDIM];
__device__ __align__(16) float g_v[NKVH * SQ * HDIM];
__device__ __align__(16) bf g_vT_h[NKVH * HDIM * SQ];
__device__ __align__(16) bf g_vT_l[NKVH * HDIM * SQ];
__device__ __align__(16) float g_e[(size_t)NHEAD * SQ * SQ];
__device__ __align__(16) bf g_p_h[(size_t)NHEAD * SQ * SQ];
__device__ __align__(16) bf g_p_l[(size_t)NHEAD * SQ * SQ];
__device__ __align__(16) bf g_ao_h[SQ * HIDN];
__device__ __align__(16) bf g_ao_l[SQ * HIDN];
__device__ float g_bias[QKV_N];
__device__ float g_invrsum[NHEAD * SQ];
__device__ float g_colsum[NHEAD * SQ];
__device__ unsigned char g_heavy[NHEAD * SQ];

// ---------------- small helpers ----------------
static __device__ __forceinline__ void split2(float x, bf& h, bf& l) {
    h = __float2bfloat16_rn(x);
    l = __float2bfloat16_rn(x - __bfloat162float(h));
}
static __device__ __forceinline__ u32 packbf(bf a, bf b) {
    return (u32)__bfloat16_as_ushort(a) | ((u32)__bfloat16_as_ushort(b) << 16);
}
static __device__ __forceinline__ float warp_red_max(float v) {
#pragma unroll
    for (int o = 16; o > 0; o >>= 1) v = fmaxf(v, __shfl_xor_sync(0xffffffffu, v, o));
    return v;
}
static __device__ __forceinline__ float warp_red_sum(float v) {
#pragma unroll
    for (int o = 16; o > 0; o >>= 1) v += __shfl_xor_sync(0xffffffffu, v, o);
    return v;
}
// fast exp for x <= 0: FFMA-pipe polynomial (error ~1.3e-6 rel), no MUFU.
static __device__ __forceinline__ float fexp(float x) {
    float y = x * 1.4426950408889634f;
    if (y < -126.0f) return 0.0f;
    float f = floorf(y);
    float r = y - f;
    float p = 1.525273380405984e-5f;
    p = fmaf(p, r, 1.5403530393381608e-4f);
    p = fmaf(p, r, 1.3333558146428443e-3f);
    p = fmaf(p, r, 9.618129107628477e-3f);
    p = fmaf(p, r, 5.550410866482158e-2f);
    p = fmaf(p, r, 2.4022650695910072e-1f);
    p = fmaf(p, r, 6.931471805599453e-1f);
    p = fmaf(p, r, 1.0f);
    float sc = __int_as_float(((int)f + 127) << 23);
    return sc * p;
}

// ---------------- mma / ldmatrix / cp.async primitives ----------------------
static __device__ __forceinline__ void mma_tile(float* d, const u32* a, u32 b0, u32 b1) {
    asm volatile(
        "mma.sync.aligned.m16n8k16.row.col.f32.bf16.bf16.f32 "
        "{%0,%1,%2,%3}, {%4,%5,%6,%7}, {%8,%9}, {%0,%1,%2,%3};"
        : "+f"(d[0]), "+f"(d[1]), "+f"(d[2]), "+f"(d[3])
        : "r"(a[0]), "r"(a[1]), "r"(a[2]), "r"(a[3]), "r"(b0), "r"(b1));
}
static __device__ __forceinline__ void ldsm_x4(u32* r, u32 addr) {
    asm volatile("ldmatrix.sync.aligned.m8n8.x4.shared.b16 {%0,%1,%2,%3}, [%4];"
        : "=r"(r[0]), "=r"(r[1]), "=r"(r[2]), "=r"(r[3]) : "r"(addr));
}
static __device__ __forceinline__ u32 smem_u32(const void* p) {
    u32 a;
    asm("{ .reg .u64 t; cvta.to.shared.u64 t, %1; cvt.u32.u64 %0, t; }" : "=r"(a) : "l"(p));
    return a;
}
static __device__ __forceinline__ void cp16(u32 dst, const void* src) {
    asm volatile("cp.async.cg.shared.global [%0], [%1], 16;" :: "r"(dst), "l"(src));
}
#define CP_COMMIT() asm volatile("cp.async.commit_group;" ::: "memory")
#define CP_WAIT0() asm volatile("cp.async.wait_group 0;" ::: "memory")

// ---------------- bf16x3 GEMM mainloop --------------------------------------
// Block tile 256(M)x128(N), K-chunk 32, 2-stage cp.async ring, padded stride 40.
// 8 warps as 4(M)x2(N), warp tile 64x64, ldmatrix loads, pass-separated MMAs.
#define TP 40
#define ATILEB (256 * TP * 2)        // 20480 bytes
#define BTILEB (128 * TP * 2)        // 10240 bytes
#define STB (2 * ATILEB + 2 * BTILEB)   // 61440 bytes per stage
#define SMEMB (2 * STB)              // 122880 bytes

static __device__ __forceinline__ void issue_chunk(
    u32 sdst, const bf* Ah, const bf* Al, int lda,
    const bf* Bh, const bf* Bl, int ldb, int k0, int tid)
{
    // A tiles: 256 rows x 32 cols -> 1024 16B transfers each; 4 per thread.
#pragma unroll
    for (int i = 0; i < 4; i++) {
        int t = tid + (i << 8);
        int r = t >> 2, q = t & 3;
        u32 so = sdst + (u32)((r * TP + q * 8) << 1);
        const bf* s = Ah + (size_t)r * lda + k0 + q * 8;
        cp16(so, s);
        const bf* s2 = Al + (size_t)r * lda + k0 + q * 8;
        cp16(so + ATILEB, s2);
    }
    // B tiles: 128 rows -> 512 transfers each; 2 per thread.
#pragma unroll
    for (int i = 0; i < 2; i++) {
        int t = tid + (i << 8);
        int r = t >> 2, q = t & 3;
        u32 so = sdst + (u32)(2 * ATILEB) + (u32)((r * TP + q * 8) << 1);
        const bf* s = Bh + (size_t)r * ldb + k0 + q * 8;
        cp16(so, s);
        const bf* s2 = Bl + (size_t)r * ldb + k0 + q * 8;
        cp16(so + BTILEB, s2);
    }
}

static __device__ __forceinline__ void mainloop(
    bf* smem,
    const bf* __restrict__ Ah, const bf* __restrict__ Al, int lda,
    const bf* __restrict__ Bh, const bf* __restrict__ Bl, int ldb,
    int nchunk, int tid, float acc[4][8][4])
{
    int lane = tid & 31, wid = tid >> 5;
    int wm = wid & 3, wn = wid >> 2;
    u32 sbase = smem_u32(smem);
    u32 aoff = (u32)(((lane & 15) * TP + ((lane >> 4) << 3)) << 1);
    u32 boff = (u32)(((((lane & 7) + ((lane >> 4) << 3)) * TP) + (((lane >> 3) & 1) << 3)) << 1);
    u32 aA0 = sbase + aoff + (u32)((wm * 64 * TP) << 1);
    u32 bB0 = sbase + (u32)(2 * ATILEB) + boff + (u32)((wn * 64 * TP) << 1);

    issue_chunk(sbase, Ah, Al, lda, Bh, Bl, ldb, 0, tid);
    CP_COMMIT();

    for (int c = 0; c < nchunk; c++) {
        CP_WAIT0();
        __syncthreads();
        if (c + 1 < nchunk) {
            issue_chunk(sbase + (u32)(((c + 1) & 1) * STB), Ah, Al, lda, Bh, Bl, ldb,
                        (c + 1) << 5, tid);
            CP_COMMIT();
        }
        u32 stb = (u32)((c & 1) * STB);
#pragma unroll
        for (int ks = 0; ks < 32; ks += 16) {
            u32 ah[4][4], al[4][4];
#pragma unroll
            for (int mt = 0; mt < 4; mt++) {
                u32 ad = aA0 + stb + (u32)(((mt * 16 * TP) + ks) << 1);
                ldsm_x4(ah[mt], ad);
                ldsm_x4(al[mt], ad + (u32)ATILEB);
            }
#pragma unroll
            for (int nbp = 0; nbp < 4; nbp++) {
                u32 bd = bB0 + stb + (u32)(((nbp * 16 * TP) + ks) << 1);
                u32 bh[4], bl[4];
                ldsm_x4(bh, bd);
                ldsm_x4(bl, bd + (u32)BTILEB);
#pragma unroll
                for (int hh = 0; hh < 2; hh++) {
                    int nb = nbp * 2 + hh;
                    u32 b0h = bh[hh * 2], b1h = bh[hh * 2 + 1];
                    u32 b0l = bl[hh * 2], b1l = bl[hh * 2 + 1];
                    // pass-separated: 4 independent MMAs between same-acc reuse
#pragma unroll
                    for (int mt = 0; mt < 4; mt++) mma_tile(acc[mt][nb], ah[mt], b0h, b1h);
#pragma unroll
                    for (int mt = 0; mt < 4; mt++) mma_tile(acc[mt][nb], al[mt], b0h, b1h);
#pragma unroll
                    for (int mt = 0; mt < 4; mt++) mma_tile(acc[mt][nb], ah[mt], b0l, b1l);
                }
            }
        }
        __syncthreads();
    }
}

// ---------------- GEMM kernels ----------------
__global__ __launch_bounds__(256) void mm_lin(
    const bf* __restrict__ Ah, const bf* __restrict__ Al,
    const bf* __restrict__ Bh, const bf* __restrict__ Bl,
    int K, float* __restrict__ C, int ldc, const float* __restrict__ bias)
{
    extern __shared__ bf smem[];
    int tid = threadIdx.x;
    int row0 = blockIdx.y << 8, colb = blockIdx.x << 7;
    float acc[4][8][4];
#pragma unroll
    for (int a = 0; a < 4; a++)
#pragma unroll
        for (int b = 0; b < 8; b++)
#pragma unroll
            for (int c = 0; c < 4; c++) acc[a][b][c] = 0.f;

    mainloop(smem, Ah + (size_t)row0 * K, Al + (size_t)row0 * K, K,
             Bh + (size_t)colb * K, Bl + (size_t)colb * K, K, K >> 5, tid, acc);

    int lane = tid & 31, wid = tid >> 5;
    int g = lane >> 2, tig = lane & 3, wm = wid & 3, wn = wid >> 2;
#pragma unroll
    for (int mt = 0; mt < 4; mt++)
#pragma unroll
        for (int nb = 0; nb < 8; nb++) {
            int gr = row0 + wm * 64 + mt * 16 + g;
            int gc = colb + wn * 64 + nb * 8 + 2 * tig;
            float b0 = 0.f, b1 = 0.f;
            if (bias) { b0 = bias[gc]; b1 = bias[gc + 1]; }
            float* p0 = &C[(size_t)gr * ldc + gc];
            float* p1 = &C[(size_t)(gr + 8) * ldc + gc];
            p0[0] = acc[mt][nb][0] + b0; p0[1] = acc[mt][nb][1] + b1;
            p1[0] = acc[mt][nb][2] + b0; p1[1] = acc[mt][nb][3] + b1;
        }
}

__global__ __launch_bounds__(256) void mm_qk() {
    int jt = blockIdx.x, it = blockIdx.y, h = blockIdx.z;
    if (jt >= 2 * it + 2) return;           // tile fully above diagonal
    extern __shared__ bf smem[];
    int tid = threadIdx.x;
    int i0 = it << 8, j0 = jt << 7;
    size_t qo = ((size_t)h * SQ + i0) * HDIM;
    size_t ko = ((size_t)(h >> 2) * SQ + j0) * HDIM;
    float acc[4][8][4];
#pragma unroll
    for (int a = 0; a < 4; a++)
#pragma unroll
        for (int b = 0; b < 8; b++)
#pragma unroll
            for (int c = 0; c < 4; c++) acc[a][b][c] = 0.f;

    mainloop(smem, g_q_h + qo, g_q_l + qo, HDIM, g_k_h + ko, g_k_l + ko, HDIM, 4, tid, acc);

    int lane = tid & 31, wid = tid >> 5;
    int g = lane >> 2, tig = lane & 3, wm = wid & 3, wn = wid >> 2;
    const float scale = 0.08838834764831845f;
    float* E = g_e + (size_t)h * SQ * SQ;
#pragma unroll
    for (int mt = 0; mt < 4; mt++)
#pragma unroll
        for (int nb = 0; nb < 8; nb++) {
            int gi = i0 + wm * 64 + mt * 16 + g;
            int gj = j0 + wn * 64 + nb * 8 + 2 * tig;
            if (gj <= gi)     E[(size_t)gi * SQ + gj]     = acc[mt][nb][0] * scale;
            if (gj + 1 <= gi) E[(size_t)gi * SQ + gj + 1] = acc[mt][nb][1] * scale;
            int gi8 = gi + 8;
            if (gj <= gi8)     E[(size_t)gi8 * SQ + gj]     = acc[mt][nb][2] * scale;
            if (gj + 1 <= gi8) E[(size_t)gi8 * SQ + gj + 1] = acc[mt][nb][3] * scale;
        }
}

__global__ __launch_bounds__(256) void mm_av() {
    int qt = blockIdx.x, h = blockIdx.y;
    extern __shared__ bf smem[];
    int tid = threadIdx.x;
    int q0 = qt << 8;
    size_t po = ((size_t)h * SQ + q0) * SQ;
    size_t vo = (size_t)(h >> 2) * HDIM * SQ;
    float acc[4][8][4];
#pragma unroll
    for (int a = 0; a < 4; a++)
#pragma unroll
        for (int b = 0; b < 8; b++)
#pragma unroll
            for (int c = 0; c < 4; c++) acc[a][b][c] = 0.f;

    mainloop(smem, g_p_h + po, g_p_l + po, SQ, g_vT_h + vo, g_vT_l + vo, SQ,
             8 * (qt + 1), tid, acc);

    int lane = tid & 31, wid = tid >> 5;
    int g = lane >> 2, tig = lane & 3, wm = wid & 3, wn = wid >> 2;
#pragma unroll
    for (int mt = 0; mt < 4; mt++)
#pragma unroll
        for (int nb = 0; nb < 8; nb++) {
            int gq = q0 + wm * 64 + mt * 16 + g;
            int gc = wn * 64 + nb * 8 + 2 * tig;
            bf h0, l0, h1, l1;
            split2(acc[mt][nb][0], h0, l0); split2(acc[mt][nb][1], h1, l1);
            size_t o = (size_t)gq * HIDN + (h << 7) + gc;
            *(u32*)(g_ao_h + o) = packbf(h0, h1);
            *(u32*)(g_ao_l + o) = packbf(l0, l1);
            split2(acc[mt][nb][2], h0, l0); split2(acc[mt][nb][3], h1, l1);
            o = (size_t)(gq + 8) * HIDN + (h << 7) + gc;
            *(u32*)(g_ao_h + o) = packbf(h0, h1);
            *(u32*)(g_ao_l + o) = packbf(l0, l1);
        }
}

// ---------------- prep kernels ----------------
__global__ void split_rm(const float* __restrict__ src, bf* __restrict__ h,
                         bf* __restrict__ l, int n) {
    int i = blockIdx.x * blockDim.x + threadIdx.x;
    if (i < n) { bf a, b; split2(src[i], a, b); h[i] = a; l[i] = b; }
}

__global__ void catb_kernel(const float* __restrict__ bq, const float* __restrict__ bk,
                            const float* __restrict__ bv) {
    int i = blockIdx.x * blockDim.x + threadIdx.x;
    if (i < 2048) g_bias[i] = bq[i];
    else if (i < 2560) g_bias[i] = bk[i - 2048];
    else if (i < QKV_N) g_bias[i] = bv[i - 2560];
}

__global__ void split_tr(const float* __restrict__ src, int N,
                         bf* __restrict__ dh, bf* __restrict__ dl, int K) {
    __shared__ float t[32][33];
    int k0 = blockIdx.x << 5, n0 = blockIdx.y << 5;
    int tx = threadIdx.x, ty = threadIdx.y;
#pragma unroll
    for (int r = 0; r < 4; r++)
        t[ty + r * 8][tx] = src[(size_t)(k0 + ty + r * 8) * N + n0 + tx];
    __syncthreads();
#pragma unroll
    for (int r = 0; r < 4; r++) {
        int k = k0 + tx, n = n0 + ty + r * 8;
        bf a, b; split2(t[tx][ty + r * 8], a, b);
        dh[(size_t)n * K + k] = a;
        dl[(size_t)n * K + k] = b;
    }
}

__global__ void rope_kernel(const float* __restrict__ cosp, const float* __restrict__ sinp) {
    int idx = blockIdx.x * blockDim.x + threadIdx.x;
    if (idx >= SQ * QKV_N) return;
    int s = idx / QKV_N, c = idx - s * QKV_N;
    float val = g_qkv[idx];
    if (c < 2048) {
        int h = c >> 7, d = c & 127;
        float cs = cosp[s * HDIM + d], sn = sinp[s * HDIM + d];
        float other = (d < 64) ? -g_qkv[idx + 64] : g_qkv[idx - 64];
        float r = val * cs + other * sn;
        bf a, b; split2(r, a, b);
        size_t o = ((size_t)h * SQ + s) * HDIM + d;
        g_q_h[o] = a; g_q_l[o] = b;
    } else if (c < 2560) {
        int cc = c - 2048, h = cc >> 7, d = cc & 127;
        float cs = cosp[s * HDIM + d], sn = sinp[s * HDIM + d];
        float other = (d < 64) ? -g_qkv[idx + 64] : g_qkv[idx - 64];
        float r = val * cs + other * sn;
        bf a, b; split2(r, a, b);
        size_t o = ((size_t)h * SQ + s) * HDIM + d;
        g_k_h[o] = a; g_k_l[o] = b;
    } else {
        int cc = c - 2560, h = cc >> 7, d = cc & 127;
        g_v[((size_t)h * SQ + s) * HDIM + d] = val;
    }
}

__global__ void vtsplit_kernel() {
    __shared__ float t[32][33];
    int h = blockIdx.z;
    int s0 = blockIdx.x << 5, d0 = blockIdx.y << 5;
    int tx = threadIdx.x, ty = threadIdx.y;
    const float* V = g_v + (size_t)h * SQ * HDIM;
#pragma unroll
    for (int k = 0; k < 4; k++)
        t[ty + k * 8][tx] = V[(size_t)(s0 + ty + k * 8) * HDIM + d0 + tx];
    __syncthreads();
    bf* oh = g_vT_h + (size_t)h * HDIM * SQ;
    bf* ol = g_vT_l + (size_t)h * HDIM * SQ;
#pragma unroll
    for (int k = 0; k < 4; k++) {
        int d = d0 + ty + k * 8, s = s0 + tx;
        bf a, b; split2(t[tx][ty + k * 8], a, b);
        oh[(size_t)d * SQ + s] = a;
        ol[(size_t)d * SQ + s] = b;
    }
}

// ---------------- softmax / H2O passes ---------------------
__global__ void rowexp_kernel() {
    int i = blockIdx.x, h = blockIdx.y, tid = threadIdx.x;
    float* row = g_e + ((size_t)h * SQ + i) * SQ;
    int n = i + 1;
    float m = -1e30f;
    for (int j = tid; j < n; j += 128) m = fmaxf(m, row[j]);
    __shared__ float red[4];
    m = warp_red_max(m);
    if ((tid & 31) == 0) red[tid >> 5] = m;
    __syncthreads();
    m = fmaxf(fmaxf(red[0], red[1]), fmaxf(red[2], red[3]));
    float ssum = 0.f;
    for (int j = tid; j < n; j += 128) { float e = fexp(row[j] - m); row[j] = e; ssum += e; }
    __syncthreads();
    ssum = warp_red_sum(ssum);
    if ((tid & 31) == 0) red[tid >> 5] = ssum;
    __syncthreads();
    if (tid == 0) g_invrsum[h * SQ + i] = 1.0f / (red[0] + red[1] + red[2] + red[3]);
}

__global__ void colsum_kernel() {
    int h = blockIdx.y;
    int j = blockIdx.x * 256 + threadIdx.x;
    int istart = blockIdx.x * 256;
    const float* E = g_e + (size_t)h * SQ * SQ;
    float acc = 0.f;
    for (int i = istart; i < SQ; i++)
        if (i >= j) acc += E[(size_t)i * SQ + j] * g_invrsum[h * SQ + i];
    g_colsum[h * SQ + j] = acc;
}

__global__ __launch_bounds__(1024) void topk_kernel() {
    __shared__ float sv[2048];
    int h = blockIdx.x, tid = threadIdx.x;
    sv[tid] = g_colsum[h * SQ + tid];
    sv[tid + 1024] = g_colsum[h * SQ + tid + 1024];
    __syncthreads();
    for (int k = 2; k <= 2048; k <<= 1) {
        for (int j = k >> 1; j > 0; j >>= 1) {
#pragma unroll 2
            for (int base = 0; base < 2048; base += 1024) {
                int i = base + tid;
                int l = i ^ j;
                if (l > i) {
                    float a = sv[i], b = sv[l];
                    bool up = ((i & k) == 0);
                    if ((a > b) == up) { sv[i] = b; sv[l] = a; }
                }
            }
            __syncthreads();
        }
    }
    float thr = sv[2048 - HEAVY_K];
    g_heavy[h * SQ + tid]        = (g_colsum[h * SQ + tid]        >= thr) ? 1 : 0;
    g_heavy[h * SQ + tid + 1024] = (g_colsum[h * SQ + tid + 1024] >= thr) ? 1 : 0;
}

// fused: masked row sum + write normalized P (bf16 hi/lo), padded to 256-tile
__global__ void psplit_kernel() {
    int q = blockIdx.x, h = blockIdx.y, tid = threadIdx.x;
    const float* row = g_e + ((size_t)h * SQ + q) * SQ;
    const unsigned char* hv = g_heavy + h * SQ;
    float s = 0.f;
    for (int j = tid; j <= q; j += 256)
        if (hv[j] || (q - j) <= RECENT_W) s += row[j];
    __shared__ float red[8];
    s = warp_red_sum(s);
    if ((tid & 31) == 0) red[tid >> 5] = s;
    __syncthreads();
    float tot = red[0] + red[1] + red[2] + red[3] + red[4] + red[5] + red[6] + red[7];
    float inv = 1.0f / tot;
    int jmax = ((q >> 8) + 1) << 8;          // pad to 256-row AV tile
    bf* ph = g_p_h + ((size_t)h * SQ + q) * SQ;
    bf* pl = g_p_l + ((size_t)h * SQ + q) * SQ;
    for (int j = tid; j < jmax; j += 256) {
        float p = 0.f;
        if (j <= q && (hv[j] || (q - j) <= RECENT_W)) p = row[j] * inv;
        bf a, b; split2(p, a, b);
        ph[j] = a; pl[j] = b;
    }
}

// ---------------- launch ----------------
extern "C" void kernel_launch(void* const* d_in, const int* in_sizes, int n_in,
                              void* d_out, int out_size) {
    (void)in_sizes; (void)n_in; (void)out_size;
    const float* hidden = (const float*)d_in[0];
    const float* cosp   = (const float*)d_in[1];
    const float* sinp   = (const float*)d_in[2];
    const float* Wq = (const float*)d_in[4];
    const float* bq = (const float*)d_in[5];
    const float* Wk = (const float*)d_in[6];
    const float* bk = (const float*)d_in[7];
    const float* Wv = (const float*)d_in[8];
    const float* bv = (const float*)d_in[9];
    const float* Wo = (const float*)d_in[10];
    float* out = (float*)d_out;

    cudaFuncSetAttribute(mm_lin, cudaFuncAttributeMaxDynamicSharedMemorySize, SMEMB);
    cudaFuncSetAttribute(mm_qk,  cudaFuncAttributeMaxDynamicSharedMemorySize, SMEMB);
    cudaFuncSetAttribute(mm_av,  cudaFuncAttributeMaxDynamicSharedMemorySize, SMEMB);

    void* p;
    cudaGetSymbolAddress(&p, g_qkv);   float* qkv  = (float*)p;
    cudaGetSymbolAddress(&p, g_hid_h); bf* hid_h = (bf*)p;
    cudaGetSymbolAddress(&p, g_hid_l); bf* hid_l = (bf*)p;
    cudaGetSymbolAddress(&p, g_wT_h);  bf* wT_h  = (bf*)p;
    cudaGetSymbolAddress(&p, g_wT_l);  bf* wT_l  = (bf*)p;
    cudaGetSymbolAddress(&p, g_woT_h); bf* woT_h = (bf*)p;
    cudaGetSymbolAddress(&p, g_woT_l); bf* woT_l = (bf*)p;
    cudaGetSymbolAddress(&p, g_ao_h);  bf* ao_h  = (bf*)p;
    cudaGetSymbolAddress(&p, g_ao_l);  bf* ao_l  = (bf*)p;
    cudaGetSymbolAddress(&p, g_bias);  float* biasq = (float*)p;

    split_rm<<<(SQ * HIDN + 1023) / 1024, 1024>>>(hidden, hid_h, hid_l, SQ * HIDN);
    catb_kernel<<<3, 1024>>>(bq, bk, bv);
    split_tr<<<dim3(64, 64), dim3(32, 8)>>>(Wq, 2048, wT_h, wT_l, HIDN);
    split_tr<<<dim3(64, 16), dim3(32, 8)>>>(Wk, 512, wT_h + (size_t)2048 * HIDN, wT_l + (size_t)2048 * HIDN, HIDN);
    split_tr<<<dim3(64, 16), dim3(32, 8)>>>(Wv, 512, wT_h + (size_t)2560 * HIDN, wT_l + (size_t)2560 * HIDN, HIDN);
    split_tr<<<dim3(64, 64), dim3(32, 8)>>>(Wo, 2048, woT_h, woT_l, HIDN);

    // fused QKV projection (block 256x128)
    mm_lin<<<dim3(24, 8), 256, SMEMB>>>(hid_h, hid_l, wT_h, wT_l, HIDN, qkv, QKV_N, biasq);

    rope_kernel<<<(SQ * QKV_N + 255) / 256, 256>>>(cosp, sinp);
    vtsplit_kernel<<<dim3(64, 4, NKVH), dim3(32, 8)>>>();

    mm_qk<<<dim3(16, 8, NHEAD), 256, SMEMB>>>();
    rowexp_kernel<<<dim3(SQ, NHEAD), 128>>>();
    colsum_kernel<<<dim3(8, NHEAD), 256>>>();
    topk_kernel<<<NHEAD, 1024>>>();
    psplit_kernel<<<dim3(SQ, NHEAD), 256>>>();
    mm_av<<<dim3(8, NHEAD), 256, SMEMB>>>();

    // output projection
    mm_lin<<<dim3(16, 8), 256, SMEMB>>>(ao_h, ao_l, woT_h, woT_l, HIDN, out, HIDN, (const float*)nullptr);
}